// round 4
// baseline (speedup 1.0000x reference)
#include <cuda_runtime.h>
#include <cuda_bf16.h>
#include <stdint.h>

// ---------------- problem dims ----------------
#define BATCH   4
#define T_SEQ   2048
#define D_MODEL 1024
#define D_FF    4096
#define M_TOTAL (BATCH * T_SEQ)   // 8192

// ---------------- device scratch ----------------
__device__ uint8_t g_E8[M_TOTAL * D_MODEL];          // ema(spikes) e4m3      (8 MB)
__device__ float   g_Ef[(size_t)M_TOTAL * D_MODEL];  // ema(spikes) fp32      (32 MB)
__device__ uint8_t g_W18[D_FF * D_MODEL];            // 64*W1 e4m3            (4 MB)
__device__ int     g_count;
#define SPIKE_CAP (1 << 20)
__device__ int     g_list[SPIKE_CAP];

// screening threshold: scores are 64x mixed (W1 scaled by 64). 0.35 * 64.
#define FLAG_T 22.4f

// ---------------- helpers ----------------
__device__ __forceinline__ uint32_t smem_u32(const void* p) {
    return (uint32_t)__cvta_generic_to_shared(p);
}
__device__ __forceinline__ void cp_async16(uint32_t saddr, const void* gaddr) {
    asm volatile("cp.async.cg.shared.global [%0], [%1], 16;\n" :: "r"(saddr), "l"(gaddr));
}
__device__ __forceinline__ void cp_commit() {
    asm volatile("cp.async.commit_group;\n" ::);
}
template <int N>
__device__ __forceinline__ void cp_wait() {
    asm volatile("cp.async.wait_group %0;\n" :: "n"(N));
}
__device__ __forceinline__ void ldmatrix_x4(uint32_t* r, uint32_t addr) {
    asm volatile("ldmatrix.sync.aligned.m8n8.x4.shared.b16 {%0,%1,%2,%3}, [%4];\n"
                 : "=r"(r[0]), "=r"(r[1]), "=r"(r[2]), "=r"(r[3]) : "r"(addr));
}
// fp8 e4m3 MMA: m16n8k32, fp32 accumulate (sm_89+ baseline PTX, NOT an 'a' feature)
__device__ __forceinline__ void mma_fp8(float* c, const uint32_t* a, const uint32_t* b) {
    asm volatile(
        "mma.sync.aligned.m16n8k32.row.col.f32.e4m3.e4m3.f32 "
        "{%0,%1,%2,%3}, {%4,%5,%6,%7}, {%8,%9}, {%0,%1,%2,%3};\n"
        : "+f"(c[0]), "+f"(c[1]), "+f"(c[2]), "+f"(c[3])
        : "r"(a[0]), "r"(a[1]), "r"(a[2]), "r"(a[3]), "r"(b[0]), "r"(b[1]));
}
__device__ __forceinline__ uint8_t f2e4m3(float v) {
    unsigned short u;
    asm("cvt.rn.satfinite.e4m3x2.f32 %0, %1, %2;" : "=h"(u) : "f"(0.f), "f"(v));
    return (uint8_t)u;   // low byte = last operand
}

// ---------------- W1 fp32 -> e4m3 (scaled by 64 to escape subnormal range) ----------------
__global__ void cvt_w1_fp8(const float4* __restrict__ in) {
    int i = blockIdx.x * blockDim.x + threadIdx.x;
    int stride = gridDim.x * blockDim.x;
    int n4 = (D_FF * D_MODEL) / 4;
    uint32_t* out = reinterpret_cast<uint32_t*>(g_W18);
    for (; i < n4; i += stride) {
        float4 v = in[i];
        unsigned short lo, hi;
        asm("cvt.rn.satfinite.e4m3x2.f32 %0, %1, %2;" : "=h"(lo) : "f"(v.y * 64.f), "f"(v.x * 64.f));
        asm("cvt.rn.satfinite.e4m3x2.f32 %0, %1, %2;" : "=h"(hi) : "f"(v.w * 64.f), "f"(v.z * 64.f));
        out[i] = (uint32_t)lo | ((uint32_t)hi << 16);
    }
}

// ---------------- EMA pre-scan (chunk 128, halo 128; 0.9^128 ~ 1.4e-6) ----------------
__global__ void __launch_bounds__(256) ema_kernel(const float* __restrict__ spikes) {
    int idx = blockIdx.x * 256 + threadIdx.x;     // 0 .. 65535
    int d = idx & (D_MODEL - 1);
    int q = idx >> 10;                            // 0..63
    int b = q >> 4;
    int c = q & 15;
    const float* sp = spikes + (size_t)b * T_SEQ * D_MODEL + d;
    float*   ef = g_Ef + (size_t)b * T_SEQ * D_MODEL + d;
    uint8_t* e8 = g_E8 + (size_t)b * T_SEQ * D_MODEL + d;
    int t0 = c * 128;
    float acc = 0.f;
    if (c) {
        for (int t = t0 - 128; t < t0; t += 8) {
            float v[8];
#pragma unroll
            for (int i = 0; i < 8; i++) v[i] = sp[(size_t)(t + i) * D_MODEL];
#pragma unroll
            for (int i = 0; i < 8; i++) acc = fmaf(0.9f, acc, 0.1f * v[i]);
        }
    }
    for (int t = t0; t < t0 + 128; t += 8) {
        float v[8];
#pragma unroll
        for (int i = 0; i < 8; i++) v[i] = sp[(size_t)(t + i) * D_MODEL];
#pragma unroll
        for (int i = 0; i < 8; i++) {
            acc = fmaf(0.9f, acc, 0.1f * v[i]);
            ef[(size_t)(t + i) * D_MODEL] = acc;
            e8[(size_t)(t + i) * D_MODEL] = f2e4m3(acc);
        }
    }
}

__global__ void reset_count_kernel() {
    if (threadIdx.x == 0 && blockIdx.x == 0) g_count = 0;
}

// ---------------- FP8 GEMM screen: score = E8[m] . W18[n], flag > FLAG_T ----------------
// CTA tile 128x128, 64 fp8 k-bytes/stage, 4-stage cp.async, 8 warps (2x4), warp tile 64x32.
// fp8 m16n8k32 fragments are byte-identical to bf16 m16n8k16 fragments (k-pairs = b16).
#define ROW_B   80                           // padded row stride in bytes (conflict-free)
#define STAGE_A (128 * ROW_B)                // 10240
#define STAGE_BYTES (2 * STAGE_A)            // 20480
#define NSTAGE  4
#define GEMM_SMEM (NSTAGE * STAGE_BYTES)     // 81920

__global__ void __launch_bounds__(256) gemm_screen_kernel() {
    extern __shared__ __align__(128) char smem[];
    uint32_t sb = smem_u32(smem);

    const int tid  = threadIdx.x;
    const int lane = tid & 31;
    const int w    = tid >> 5;
    const int wm   = w & 1;
    const int wn   = w >> 1;
    const int m0   = blockIdx.y * 128;
    const int n0   = blockIdx.x * 128;

    float acc[4][4][4];
#pragma unroll
    for (int i = 0; i < 4; i++)
#pragma unroll
        for (int j = 0; j < 4; j++)
#pragma unroll
            for (int e = 0; e < 4; e++) acc[i][j][e] = 0.f;

    auto fill = [&](int buf, int kt) {
        uint32_t base = sb + buf * STAGE_BYTES;
        const int k0 = kt * 64;
#pragma unroll
        for (int i = 0; i < 2; i++) {            // A: 512 16B chunks
            int ci = tid + i * 256;
            int row = ci >> 2, ck = ci & 3;
            cp_async16(base + row * ROW_B + ck * 16,
                       g_E8 + (size_t)(m0 + row) * D_MODEL + k0 + ck * 16);
        }
#pragma unroll
        for (int i = 0; i < 2; i++) {            // B: 512 16B chunks
            int ci = tid + i * 256;
            int row = ci >> 2, ck = ci & 3;
            cp_async16(base + STAGE_A + row * ROW_B + ck * 16,
                       g_W18 + (size_t)(n0 + row) * D_MODEL + k0 + ck * 16);
        }
    };

    auto compute = [&](int buf) {
        uint32_t abase = sb + buf * STAGE_BYTES;
        uint32_t bbase = abase + STAGE_A;
#pragma unroll
        for (int kk = 0; kk < 2; kk++) {         // two 32-fp8 sub-tiles
            uint32_t a[4][4], b[4][2];
#pragma unroll
            for (int i = 0; i < 4; i++) {
                int arow = wm * 64 + i * 16 + (lane & 15);
                uint32_t abyte = arow * ROW_B + kk * 32 + (lane >> 4) * 16;
                ldmatrix_x4(a[i], abase + abyte);
            }
#pragma unroll
            for (int j = 0; j < 2; j++) {
                int brow = wn * 32 + j * 16 + (lane & 7) + ((lane >> 4) << 3);
                uint32_t bbyte = brow * ROW_B + kk * 32 + ((lane >> 3) & 1) * 16;
                uint32_t r[4];
                ldmatrix_x4(r, bbase + bbyte);
                b[2 * j][0] = r[0]; b[2 * j][1] = r[1];
                b[2 * j + 1][0] = r[2]; b[2 * j + 1][1] = r[3];
            }
#pragma unroll
            for (int i = 0; i < 4; i++)
#pragma unroll
                for (int jn = 0; jn < 4; jn++)
                    mma_fp8(acc[i][jn], a[i], b[jn]);
        }
    };

    fill(0, 0); cp_commit();
    fill(1, 1); cp_commit();
    fill(2, 2); cp_commit();

    const int KT = D_MODEL / 64;   // 16
    for (int kt = 0; kt < KT; kt++) {
        cp_wait<2>();
        __syncthreads();
        if (kt + 3 < KT) fill((kt + 3) & 3, kt + 3);
        cp_commit();
        compute(kt & 3);
    }

    // epilogue: flag candidates only (no dense stores at all)
#pragma unroll
    for (int i = 0; i < 4; i++) {
#pragma unroll
        for (int jn = 0; jn < 4; jn++) {
            int row = m0 + wm * 64 + i * 16 + (lane >> 2);
            int col = n0 + wn * 32 + jn * 8 + (lane & 3) * 2;
#pragma unroll
            for (int e = 0; e < 4; e++) {
                if (acc[i][jn][e] > FLAG_T) {
                    int r = row + (e >> 1) * 8;
                    int c = col + (e & 1);
                    int pos = atomicAdd(&g_count, 1);
                    if (pos < SPIKE_CAP) g_list[pos] = r * D_FF + c;
                }
            }
        }
    }
}

// ---------------- exact recheck + fixup for flagged candidates (expected ~0-100) ----------------
__global__ void recheck_fixup_kernel(const float* __restrict__ spikes,
                                     const float* __restrict__ W1,
                                     const float* __restrict__ Wr,
                                     const float* __restrict__ W2,
                                     float* __restrict__ out) {
    __shared__ float red[256];
    __shared__ float bcast;
    int c = g_count;
    if (c > SPIKE_CAP) c = SPIKE_CAP;
    for (int i = blockIdx.x; i < c; i += gridDim.x) {
        int g  = g_list[i];
        int f  = g & (D_FF - 1);
        int bt = g >> 12;
        // exact fp32 mixed = ema(spikes)[bt] . W1[f]
        const float* ef = g_Ef + (size_t)bt * D_MODEL;
        const float* w1 = W1 + (size_t)f * D_MODEL;
        float s = 0.f;
        for (int d = threadIdx.x; d < D_MODEL; d += blockDim.x) s += ef[d] * w1[d];
        red[threadIdx.x] = s;
        __syncthreads();
        for (int o = 128; o > 0; o >>= 1) {
            if (threadIdx.x < o) red[threadIdx.x] += red[threadIdx.x + o];
            __syncthreads();
        }
        if (threadIdx.x == 0) bcast = red[0];
        __syncthreads();
        if (bcast > 0.5f) {   // real fire: exact receptance + rank-1 update
            const float* sp = spikes + (size_t)bt * D_MODEL;
            const float* wr = Wr + (size_t)f * D_MODEL;
            float s2 = 0.f;
            for (int d = threadIdx.x; d < D_MODEL; d += blockDim.x) s2 += sp[d] * wr[d];
            red[threadIdx.x] = s2;
            __syncthreads();
            for (int o = 128; o > 0; o >>= 1) {
                if (threadIdx.x < o) red[threadIdx.x] += red[threadIdx.x + o];
                __syncthreads();
            }
            float rv = 1.f / (1.f + expf(-red[0]));
            float* op = out + (size_t)bt * D_MODEL;
            for (int d = threadIdx.x; d < D_MODEL; d += blockDim.x)
                atomicAdd(&op[d], rv * W2[(size_t)d * D_FF + f]);
        }
        __syncthreads();
    }
}

// ---------------- launch ----------------
extern "C" void kernel_launch(void* const* d_in, const int* in_sizes, int n_in,
                              void* d_out, int out_size) {
    const float* spikes = (const float*)d_in[0];  // [B, T, D]
    const float* W1 = (const float*)d_in[1];      // [F, D]
    const float* W2 = (const float*)d_in[2];      // [D, F]
    const float* Wr = (const float*)d_in[3];      // [F, D]
    float* out = (float*)d_out;

    cudaFuncSetAttribute(gemm_screen_kernel,
                         cudaFuncAttributeMaxDynamicSharedMemorySize, GEMM_SMEM);

    cvt_w1_fp8<<<1024, 256>>>((const float4*)W1);
    ema_kernel<<<256, 256>>>(spikes);
    reset_count_kernel<<<1, 32>>>();

    dim3 grid(D_FF / 128, M_TOTAL / 128);         // (32, 64) — launch index 3
    gemm_screen_kernel<<<grid, 256, GEMM_SMEM>>>();

    cudaMemsetAsync(d_out, 0, (size_t)out_size * sizeof(float), 0);
    recheck_fixup_kernel<<<128, 256>>>(spikes, W1, Wr, W2, out);
}

// round 5
// speedup vs baseline: 1.2531x; 1.2531x over previous
#include <cuda_runtime.h>
#include <cuda_bf16.h>
#include <stdint.h>

// ---------------- problem dims ----------------
#define BATCH   4
#define T_SEQ   2048
#define D_MODEL 1024
#define D_FF    4096
#define M_TOTAL (BATCH * T_SEQ)   // 8192

// ---------------- device scratch ----------------
__device__ __nv_bfloat16 g_E[M_TOTAL * D_MODEL];     // ema(spikes) bf16 (16 MB)
__device__ float g_Ef[(size_t)M_TOTAL * D_MODEL];    // ema(spikes) fp32 (32 MB)
__device__ __nv_bfloat16 g_W1b[D_FF * D_MODEL];      // W1 bf16          (8 MB)
__device__ int g_count;
#define SPIKE_CAP (1 << 20)
__device__ int g_list[SPIKE_CAP];

#define FLAG_T 0.35f      // screen margin; exact recheck decides vs 0.5

// ---------------- helpers ----------------
__device__ __forceinline__ uint32_t smem_u32(const void* p) {
    return (uint32_t)__cvta_generic_to_shared(p);
}
__device__ __forceinline__ void cp_async16(uint32_t saddr, const void* gaddr) {
    asm volatile("cp.async.cg.shared.global [%0], [%1], 16;\n" :: "r"(saddr), "l"(gaddr));
}
__device__ __forceinline__ void cp_commit() {
    asm volatile("cp.async.commit_group;\n" ::);
}
template <int N>
__device__ __forceinline__ void cp_wait() {
    asm volatile("cp.async.wait_group %0;\n" :: "n"(N));
}
__device__ __forceinline__ void ldmatrix_x4(uint32_t* r, uint32_t addr) {
    asm volatile("ldmatrix.sync.aligned.m8n8.x4.shared.b16 {%0,%1,%2,%3}, [%4];\n"
                 : "=r"(r[0]), "=r"(r[1]), "=r"(r[2]), "=r"(r[3]) : "r"(addr));
}
__device__ __forceinline__ void mma_bf16(float* c, const uint32_t* a, const uint32_t* b) {
    asm volatile(
        "mma.sync.aligned.m16n8k16.row.col.f32.bf16.bf16.f32 "
        "{%0,%1,%2,%3}, {%4,%5,%6,%7}, {%8,%9}, {%0,%1,%2,%3};\n"
        : "+f"(c[0]), "+f"(c[1]), "+f"(c[2]), "+f"(c[3])
        : "r"(a[0]), "r"(a[1]), "r"(a[2]), "r"(a[3]), "r"(b[0]), "r"(b[1]));
}

// ---------------- W1 fp32 -> bf16 (+ reset spike counter) ----------------
__global__ void cvt_w1(const float4* __restrict__ in) {
    if (blockIdx.x == 0 && threadIdx.x == 0) g_count = 0;
    int i = blockIdx.x * blockDim.x + threadIdx.x;
    int stride = gridDim.x * blockDim.x;
    int n4 = (D_FF * D_MODEL) / 4;
    uint2* out = reinterpret_cast<uint2*>(g_W1b);
    for (; i < n4; i += stride) {
        float4 v = in[i];
        uint32_t p0, p1;
        asm("cvt.rn.bf16x2.f32 %0, %1, %2;" : "=r"(p0) : "f"(v.y), "f"(v.x));
        asm("cvt.rn.bf16x2.f32 %0, %1, %2;" : "=r"(p1) : "f"(v.w), "f"(v.z));
        out[i] = make_uint2(p0, p1);
    }
}

// ---------------- EMA pre-scan (chunk 128, halo 128; 0.9^128 ~ 1.4e-6) ----------------
__global__ void __launch_bounds__(256) ema_kernel(const float* __restrict__ spikes) {
    int idx = blockIdx.x * 256 + threadIdx.x;     // 0 .. 65535
    int d = idx & (D_MODEL - 1);
    int q = idx >> 10;                            // 0..63
    int b = q >> 4;
    int c = q & 15;
    const float* sp = spikes + (size_t)b * T_SEQ * D_MODEL + d;
    float* ef = g_Ef + (size_t)b * T_SEQ * D_MODEL + d;
    __nv_bfloat16* eb = g_E + (size_t)b * T_SEQ * D_MODEL + d;
    int t0 = c * 128;
    float acc = 0.f;
    if (c) {
        for (int t = t0 - 128; t < t0; t += 8) {
            float v[8];
#pragma unroll
            for (int i = 0; i < 8; i++) v[i] = sp[(size_t)(t + i) * D_MODEL];
#pragma unroll
            for (int i = 0; i < 8; i++) acc = fmaf(0.9f, acc, 0.1f * v[i]);
        }
    }
    for (int t = t0; t < t0 + 128; t += 8) {
        float v[8];
#pragma unroll
        for (int i = 0; i < 8; i++) v[i] = sp[(size_t)(t + i) * D_MODEL];
#pragma unroll
        for (int i = 0; i < 8; i++) {
            acc = fmaf(0.9f, acc, 0.1f * v[i]);
            ef[(size_t)(t + i) * D_MODEL] = acc;
            eb[(size_t)(t + i) * D_MODEL] = __float2bfloat16(acc);
        }
    }
}

// ---------------- bf16 GEMM screen, 3-stage cp.async, BK=64, 1 barrier/step ----------------
// CTA tile 128x128, 8 warps (2 M x 4 N), warp tile 64x32.
#define BK      64
#define ROW_B   144                          // 128B row + 16B pad: conflict-free ldmatrix
#define TILE_B  (128 * ROW_B)                // 18432 per operand tile
#define STAGE_BYTES (2 * TILE_B)             // 36864
#define NSTAGE  3
#define GEMM_SMEM (NSTAGE * STAGE_BYTES)     // 110592 -> 2 CTAs/SM

__global__ void __launch_bounds__(256) gemm_screen_kernel() {
    extern __shared__ __align__(128) char smem[];
    uint32_t sb = smem_u32(smem);

    const int tid  = threadIdx.x;
    const int lane = tid & 31;
    const int w    = tid >> 5;
    const int wm   = w & 1;
    const int wn   = w >> 1;
    const int m0   = blockIdx.y * 128;
    const int n0   = blockIdx.x * 128;

    float acc[4][4][4];
#pragma unroll
    for (int i = 0; i < 4; i++)
#pragma unroll
        for (int j = 0; j < 4; j++)
#pragma unroll
            for (int e = 0; e < 4; e++) acc[i][j][e] = 0.f;

    const int lrow = tid >> 3;          // 0..31 base row (x4 per op)
    const int lck  = tid & 7;           // 16B chunk in row

    auto fill = [&](int buf, int kt) {
        uint32_t base = sb + buf * STAGE_BYTES;
        const int k0 = kt * BK;
        const __nv_bfloat16* ga = g_E   + (size_t)(m0 + lrow) * D_MODEL + k0 + lck * 8;
        const __nv_bfloat16* gb = g_W1b + (size_t)(n0 + lrow) * D_MODEL + k0 + lck * 8;
        uint32_t sa = base + lrow * ROW_B + lck * 16;
        uint32_t sbb = base + TILE_B + lrow * ROW_B + lck * 16;
#pragma unroll
        for (int i = 0; i < 4; i++) {   // rows lrow, lrow+32, lrow+64, lrow+96
            cp_async16(sa + i * 32 * ROW_B, ga + (size_t)(i * 32) * D_MODEL);
            cp_async16(sbb + i * 32 * ROW_B, gb + (size_t)(i * 32) * D_MODEL);
        }
    };

    auto compute = [&](int buf) {
        uint32_t abase = sb + buf * STAGE_BYTES
                       + (wm * 64 + (lane & 15)) * ROW_B + (lane >> 4) * 16;
        uint32_t bbase = sb + buf * STAGE_BYTES + TILE_B
                       + (wn * 32 + (lane & 7) + ((lane >> 4) << 3)) * ROW_B
                       + ((lane >> 3) & 1) * 16;
#pragma unroll
        for (int kk = 0; kk < BK; kk += 16) {
            uint32_t a[4][4], b[4][2];
#pragma unroll
            for (int i = 0; i < 4; i++)
                ldmatrix_x4(a[i], abase + i * 16 * ROW_B + kk * 2);
#pragma unroll
            for (int j = 0; j < 2; j++) {
                uint32_t r[4];
                ldmatrix_x4(r, bbase + j * 16 * ROW_B + kk * 2);
                b[2 * j][0] = r[0]; b[2 * j][1] = r[1];
                b[2 * j + 1][0] = r[2]; b[2 * j + 1][1] = r[3];
            }
#pragma unroll
            for (int i = 0; i < 4; i++)
#pragma unroll
                for (int jn = 0; jn < 4; jn++)
                    mma_bf16(acc[i][jn], a[i], b[jn]);
        }
    };

    fill(0, 0); cp_commit();
    fill(1, 1); cp_commit();

    const int KT = D_MODEL / BK;   // 16
    for (int kt = 0; kt < KT; kt++) {
        cp_wait<1>();
        __syncthreads();
        if (kt + 2 < KT) fill((kt + 2) % NSTAGE, kt + 2);
        cp_commit();               // empty groups at tail keep wait<1> exact
        compute(kt % NSTAGE);
    }

    // epilogue: flag screen candidates only (no dense stores)
#pragma unroll
    for (int i = 0; i < 4; i++) {
#pragma unroll
        for (int jn = 0; jn < 4; jn++) {
            int row = m0 + wm * 64 + i * 16 + (lane >> 2);
            int col = n0 + wn * 32 + jn * 8 + (lane & 3) * 2;
#pragma unroll
            for (int e = 0; e < 4; e++) {
                if (acc[i][jn][e] > FLAG_T) {
                    int r = row + (e >> 1) * 8;
                    int c = col + (e & 1);
                    int pos = atomicAdd(&g_count, 1);
                    if (pos < SPIKE_CAP) g_list[pos] = r * D_FF + c;
                }
            }
        }
    }
}

// ---------------- exact recheck + fixup for flagged candidates (expected ~0) ----------------
__global__ void recheck_fixup_kernel(const float* __restrict__ spikes,
                                     const float* __restrict__ W1,
                                     const float* __restrict__ Wr,
                                     const float* __restrict__ W2,
                                     float* __restrict__ out) {
    __shared__ float red[256];
    __shared__ float bcast;
    int c = g_count;
    if (c > SPIKE_CAP) c = SPIKE_CAP;
    for (int i = blockIdx.x; i < c; i += gridDim.x) {
        int g  = g_list[i];
        int f  = g & (D_FF - 1);
        int bt = g >> 12;
        const float* ef = g_Ef + (size_t)bt * D_MODEL;
        const float* w1 = W1 + (size_t)f * D_MODEL;
        float s = 0.f;
        for (int d = threadIdx.x; d < D_MODEL; d += blockDim.x) s += ef[d] * w1[d];
        red[threadIdx.x] = s;
        __syncthreads();
        for (int o = 128; o > 0; o >>= 1) {
            if (threadIdx.x < o) red[threadIdx.x] += red[threadIdx.x + o];
            __syncthreads();
        }
        if (threadIdx.x == 0) bcast = red[0];
        __syncthreads();
        if (bcast > 0.5f) {
            const float* sp = spikes + (size_t)bt * D_MODEL;
            const float* wr = Wr + (size_t)f * D_MODEL;
            float s2 = 0.f;
            for (int d = threadIdx.x; d < D_MODEL; d += blockDim.x) s2 += sp[d] * wr[d];
            red[threadIdx.x] = s2;
            __syncthreads();
            for (int o = 128; o > 0; o >>= 1) {
                if (threadIdx.x < o) red[threadIdx.x] += red[threadIdx.x + o];
                __syncthreads();
            }
            float rv = 1.f / (1.f + expf(-red[0]));
            float* op = out + (size_t)bt * D_MODEL;
            for (int d = threadIdx.x; d < D_MODEL; d += blockDim.x)
                atomicAdd(&op[d], rv * W2[(size_t)d * D_FF + f]);
        }
        __syncthreads();
    }
}

// ---------------- launch ----------------
extern "C" void kernel_launch(void* const* d_in, const int* in_sizes, int n_in,
                              void* d_out, int out_size) {
    const float* spikes = (const float*)d_in[0];  // [B, T, D]
    const float* W1 = (const float*)d_in[1];      // [F, D]
    const float* W2 = (const float*)d_in[2];      // [D, F]
    const float* Wr = (const float*)d_in[3];      // [F, D]
    float* out = (float*)d_out;

    cudaFuncSetAttribute(gemm_screen_kernel,
                         cudaFuncAttributeMaxDynamicSharedMemorySize, GEMM_SMEM);

    cvt_w1<<<1024, 256>>>((const float4*)W1);     // also resets g_count
    ema_kernel<<<256, 256>>>(spikes);
    cudaMemsetAsync(d_out, 0, (size_t)out_size * sizeof(float), 0);

    dim3 grid(D_FF / 128, M_TOTAL / 128);         // (32, 64) — launch index 3
    gemm_screen_kernel<<<grid, 256, GEMM_SMEM>>>();

    recheck_fixup_kernel<<<128, 256>>>(spikes, W1, Wr, W2, out);
}